// round 7
// baseline (speedup 1.0000x reference)
#include <cuda_runtime.h>
#include <math.h>

#define Nn   12288
#define Ee   393216
#define Bb   16
#define FIN  15
#define Hh   32
#define H2   64
#define NC   11

// ---------------- scratch (static device globals; no allocs) ----------------
__device__ float  g_ew[Ee];
__device__ int    g_cnt[Nn];
__device__ int    g_rowptr[Nn + 1];
__device__ int    g_woff[Nn];
__device__ float  g_deg[Nn];
__device__ float2 g_pack[Ee];          // (col bits, val = ew * dis[col])

__device__ float g_x16[Nn * 16];       // x padded 15 -> 16 for float4 gathers
__device__ float g_z1[Nn * Hh];
__device__ float g_z2[Nn * H2];
__device__ float g_z3[Nn * H2];

__device__ float g_sum[3 * 64];
__device__ float g_sq [3 * 64];

__device__ float g_emb[Bb * 64];
__device__ float g_fc1[Bb * 512];
__device__ float g_fc2[Bb * 256];

// ---------------- init + pad x ----------------
__global__ void k_init(const float* __restrict__ x) {
    int i = blockIdx.x * blockDim.x + threadIdx.x;
    if (i < Nn * 16) {
        int f = i & 15;
        g_x16[i] = (f < FIN) ? x[(i >> 4) * FIN + f] : 0.f;
    }
    if (i < Nn) { g_cnt[i] = 0; g_woff[i] = 0; g_deg[i] = 0.f; }
    if (i < 3 * 64) { g_sum[i] = 0.f; g_sq[i] = 0.f; }
    if (i < Bb * 64) g_emb[i] = 0.f;
}

// 2 edges per thread: independent chains for latency hiding
__global__ void k_edge(const float* __restrict__ ea, const float* __restrict__ we,
                       const float* __restrict__ be, const int* __restrict__ ei) {
    int t = blockIdx.x * blockDim.x + threadIdx.x;
    if (t >= Ee / 2) return;
    float4 a = ((const float4*)ea)[t];          // 2 edges' attrs
    int2   r = ((const int2*)ei)[t];            // 2 rows
    float w0 = 1.f / (1.f + __expf(-(a.x * we[0] + a.y * we[1] + be[0])));
    float w1 = 1.f / (1.f + __expf(-(a.z * we[0] + a.w * we[1] + be[0])));
    ((float2*)g_ew)[t] = make_float2(w0, w1);
    atomicAdd(&g_cnt[r.x], 1);
    atomicAdd(&g_cnt[r.y], 1);
    atomicAdd(&g_deg[r.x], w0);
    atomicAdd(&g_deg[r.y], w1);
}

// single-block exclusive scan of g_cnt -> g_rowptr
__global__ void k_scan() {
    __shared__ int sh[1024];
    int t = threadIdx.x;
    const int C = Nn / 1024;  // 12
    int base = t * C;
    int pre[C];
    int s = 0;
    #pragma unroll
    for (int c = 0; c < C; c++) { pre[c] = s; s += g_cnt[base + c]; }
    sh[t] = s;
    __syncthreads();
    for (int d = 1; d < 1024; d <<= 1) {
        int v = (t >= d) ? sh[t - d] : 0;
        __syncthreads();
        sh[t] += v;
        __syncthreads();
    }
    int off = (t > 0) ? sh[t - 1] : 0;
    #pragma unroll
    for (int c = 0; c < C; c++) g_rowptr[base + c] = off + pre[c];
    if (t == 1023) g_rowptr[Nn] = sh[1023];
}

// 2 edges per thread
__global__ void k_scatter(const int* __restrict__ ei) {
    int t = blockIdx.x * blockDim.x + threadIdx.x;
    if (t >= Ee / 2) return;
    int2   r = ((const int2*)ei)[t];
    int2   c = ((const int2*)(ei + Ee))[t];
    float2 w = ((const float2*)g_ew)[t];
    float v0 = w.x * rsqrtf(1.f + g_deg[c.x]);
    float v1 = w.y * rsqrtf(1.f + g_deg[c.y]);
    int p0 = g_rowptr[r.x] + atomicAdd(&g_woff[r.x], 1);
    int p1 = g_rowptr[r.y] + atomicAdd(&g_woff[r.y], 1);
    g_pack[p0] = make_float2(__int_as_float(c.x), v0);
    g_pack[p1] = make_float2(__int_as_float(c.y), v1);
}

// ---- fused GCN layer: (BN+ReLU of prev inline) -> SpMM -> GEMM -> BN stats ----
// Warp splits into EPW = 32/LPE edge slots, LPE = FI/4 lanes each; each slot
// gathers a full feature row as float4s. Chunk body is compile-time unrolled:
// the tail chunk is padded with (col=0, w=0) entries (zero contribution,
// row-0 gathers stay L1-resident).
template <int FI, int FIeff, int FO, bool BN_IN, int GRID>
__global__ void __launch_bounds__(256) k_layer(
    const float* __restrict__ in,
    const float* __restrict__ W,         // [FIeff,FO]
    const float* __restrict__ bias,
    const float* __restrict__ gam, const float* __restrict__ bet,
    const float* __restrict__ sum_in, const float* __restrict__ sq_in,
    float* __restrict__ out,
    float* __restrict__ sum_out, float* __restrict__ sq_out)
{
    constexpr int LPE = FI / 4;
    constexpr int EPW = 32 / LPE;
    __shared__ float  sW[FIeff * FO];
    __shared__ float4 sRow4[8][16];
    __shared__ float  sScale[FI], sShift[FI];
    __shared__ float  sSum[FO], sSq[FO];
    int tid = threadIdx.x;
    for (int i = tid; i < FIeff * FO; i += 256) sW[i] = W[i];
    if (tid < FO) { sSum[tid] = 0.f; sSq[tid] = 0.f; }
    if (tid < FI) {
        if (BN_IN) {
            float mu  = sum_in[tid] * (1.f / (float)Nn);
            float var = sq_in[tid]  * (1.f / (float)Nn) - mu * mu;
            float inv = rsqrtf(var + 1e-5f);
            float sc  = gam[tid] * inv;
            sScale[tid] = sc;
            sShift[tid] = bet[tid] - sc * mu;
        } else { sScale[tid] = 1.f; sShift[tid] = 0.f; }
    }
    __syncthreads();

    int warp = tid >> 5, lane = tid & 31;
    int eh = lane / LPE;        // edge slot
    int fl = lane % LPE;        // feature quad
    float4 sc4, sh4;
    sc4.x = sScale[4*fl+0]; sc4.y = sScale[4*fl+1];
    sc4.z = sScale[4*fl+2]; sc4.w = sScale[4*fl+3];
    sh4.x = sShift[4*fl+0]; sh4.y = sShift[4*fl+1];
    sh4.z = sShift[4*fl+2]; sh4.w = sShift[4*fl+3];
    float b0 = (lane < FO) ? bias[lane] : 0.f;
    float b1 = (FO > 32) ? bias[lane + 32] : 0.f;

    const float4* in4 = (const float4*)in;
    const int RPW = Nn / (GRID * 8);
    int rowBase = (blockIdx.x * 8 + warp) * RPW;

    for (int rr = 0; rr < RPW; rr++) {
        int row = rowBase + rr;
        float d = rsqrtf(1.f + g_deg[row]);
        int s = g_rowptr[row], e = g_rowptr[row + 1];

        float4 acc = make_float4(0.f, 0.f, 0.f, 0.f);
        if (eh == 0) {   // self-loop (weight 1): d * bnrelu(in[row])
            float4 v = in4[row * LPE + fl];
            if (BN_IN) {
                v.x = fmaxf(fmaf(sc4.x, v.x, sh4.x), 0.f);
                v.y = fmaxf(fmaf(sc4.y, v.y, sh4.y), 0.f);
                v.z = fmaxf(fmaf(sc4.z, v.z, sh4.z), 0.f);
                v.w = fmaxf(fmaf(sc4.w, v.w, sh4.w), 0.f);
            }
            acc.x = d * v.x; acc.y = d * v.y; acc.z = d * v.z; acc.w = d * v.w;
        }

        for (int k = s; k < e; k += 32) {
            float2 pk = (k + lane < e) ? __ldg(&g_pack[k + lane])
                                       : make_float2(__int_as_float(0), 0.f);
            #pragma unroll
            for (int j = 0; j < 32; j += EPW) {
                int src = j + eh;
                int   c = __float_as_int(__shfl_sync(0xffffffffu, pk.x, src));
                float w = __shfl_sync(0xffffffffu, pk.y, src);
                float4 v = in4[c * LPE + fl];
                if (BN_IN) {
                    v.x = fmaxf(fmaf(sc4.x, v.x, sh4.x), 0.f);
                    v.y = fmaxf(fmaf(sc4.y, v.y, sh4.y), 0.f);
                    v.z = fmaxf(fmaf(sc4.z, v.z, sh4.z), 0.f);
                    v.w = fmaxf(fmaf(sc4.w, v.w, sh4.w), 0.f);
                }
                acc.x = fmaf(w, v.x, acc.x);
                acc.y = fmaf(w, v.y, acc.y);
                acc.z = fmaf(w, v.z, acc.z);
                acc.w = fmaf(w, v.w, acc.w);
            }
        }
        // reduce over edge slots
        #pragma unroll
        for (int o = LPE; o < 32; o <<= 1) {
            acc.x += __shfl_xor_sync(0xffffffffu, acc.x, o);
            acc.y += __shfl_xor_sync(0xffffffffu, acc.y, o);
            acc.z += __shfl_xor_sync(0xffffffffu, acc.z, o);
            acc.w += __shfl_xor_sync(0xffffffffu, acc.w, o);
        }
        acc.x *= d; acc.y *= d; acc.z *= d; acc.w *= d;
        if (eh == 0) sRow4[warp][fl] = acc;
        __syncwarp();
        const float* h = (const float*)&sRow4[warp][0];
        float o0 = b0, o1 = b1;
        #pragma unroll
        for (int f = 0; f < FIeff; f++) {
            float hv = h[f];
            o0 = fmaf(hv, sW[f * FO + lane], o0);
            if (FO > 32) o1 = fmaf(hv, sW[f * FO + lane + 32], o1);
        }
        __syncwarp();
        if (lane < FO) {
            out[row * FO + lane] = o0;
            atomicAdd(&sSum[lane], o0);
            atomicAdd(&sSq[lane],  o0 * o0);
        }
        if (FO > 32) {
            out[row * FO + lane + 32] = o1;
            atomicAdd(&sSum[lane + 32], o1);
            atomicAdd(&sSq[lane + 32],  o1 * o1);
        }
    }
    __syncthreads();
    if (tid < FO) {
        atomicAdd(&sum_out[tid], sSum[tid]);
        atomicAdd(&sq_out[tid],  sSq[tid]);
    }
}

// ---------------- max pool: sorted-batch segment flush ----------------
__global__ void __launch_bounds__(256) k_pool(
    const float* __restrict__ z3, const int* __restrict__ batch,
    const float* __restrict__ gam, const float* __restrict__ bet) {
    __shared__ float scl[64], shf[64];
    int t = threadIdx.x;
    if (t < 64) {
        float mu  = g_sum[128 + t] * (1.f / (float)Nn);
        float var = g_sq [128 + t] * (1.f / (float)Nn) - mu * mu;
        float inv = rsqrtf(var + 1e-5f);
        float sc  = gam[t] * inv;
        scl[t] = sc; shf[t] = bet[t] - sc * mu;
    }
    __syncthreads();
    int f  = t & 63;
    int r0 = blockIdx.x * 128 + (t >> 6);
    float sc = scl[f], sh = shf[f];
    int curb = -1; float cm = 0.f;
    for (int r = r0; r < blockIdx.x * 128 + 128; r += 4) {
        int b = batch[r];
        float v = fmaxf(fmaf(sc, z3[r * 64 + f], sh), 0.f);
        if (b != curb) {
            if (curb >= 0) atomicMax((int*)&g_emb[curb * 64 + f], __float_as_int(cm));
            curb = b; cm = v;
        } else cm = fmaxf(cm, v);
    }
    if (curb >= 0) atomicMax((int*)&g_emb[curb * 64 + f], __float_as_int(cm));
}

// ---------------- MLP head ----------------
__global__ void __launch_bounds__(256) k_mlp1(
    const float* __restrict__ wf1, const float* __restrict__ bf1,
    const float* __restrict__ gf1, const float* __restrict__ bef1,
    float* __restrict__ out) {
    __shared__ float se[16 * 64];
    __shared__ float sz[16][64];
    __shared__ float scl[64], shf[64];
    int t = threadIdx.x;
    for (int i = t; i < 1024; i += 256) se[i] = g_emb[i];
    __syncthreads();
    int cl = t & 63;
    int r0 = t >> 6;
    int c = blockIdx.x * 64 + cl;
    #pragma unroll
    for (int q = 0; q < 4; q++) {
        int r = r0 + q * 4;
        float a0 = 0.f, a1 = 0.f, a2 = 0.f, a3 = 0.f;
        #pragma unroll
        for (int k = 0; k < 64; k += 4) {
            a0 += se[r * 64 + k]     * wf1[(k)     * 512 + c];
            a1 += se[r * 64 + k + 1] * wf1[(k + 1) * 512 + c];
            a2 += se[r * 64 + k + 2] * wf1[(k + 2) * 512 + c];
            a3 += se[r * 64 + k + 3] * wf1[(k + 3) * 512 + c];
        }
        sz[r][cl] = bf1[c] + ((a0 + a1) + (a2 + a3));
    }
    __syncthreads();
    if (t < 64) {
        float s = 0.f, q = 0.f;
        for (int r = 0; r < 16; r++) { float v = sz[r][t]; s += v; q += v * v; }
        float mu = s * (1.f / Bb), var = q * (1.f / Bb) - mu * mu;
        float inv = rsqrtf(var + 1e-5f);
        float sc = gf1[blockIdx.x * 64 + t] * inv;
        scl[t] = sc; shf[t] = bef1[blockIdx.x * 64 + t] - sc * mu;
    }
    __syncthreads();
    #pragma unroll
    for (int q = 0; q < 4; q++) {
        int r = r0 + q * 4;
        g_fc1[r * 512 + c] = fmaxf(scl[cl] * sz[r][cl] + shf[cl], 0.f);
    }
    if (blockIdx.x == 0)
        for (int i = t; i < 1024; i += 256) out[Bb * NC + i] = se[i];
}

__global__ void __launch_bounds__(256) k_mlp2(
    const float* __restrict__ wf2, const float* __restrict__ bf2,
    const float* __restrict__ gf2, const float* __restrict__ bef2) {
    __shared__ float sf[16 * 512];
    __shared__ float sz[16][32];
    __shared__ float scl[32], shf[32];
    int t = threadIdx.x;
    for (int i = t; i < 8192; i += 256) sf[i] = g_fc1[i];
    __syncthreads();
    int cl = t & 31;
    int r0 = t >> 5;
    int c = blockIdx.x * 32 + cl;
    #pragma unroll
    for (int q = 0; q < 2; q++) {
        int r = r0 + q * 8;
        float a0 = 0.f, a1 = 0.f, a2 = 0.f, a3 = 0.f;
        for (int k = 0; k < 512; k += 4) {
            a0 += sf[r * 512 + k]     * wf2[(k)     * 256 + c];
            a1 += sf[r * 512 + k + 1] * wf2[(k + 1) * 256 + c];
            a2 += sf[r * 512 + k + 2] * wf2[(k + 2) * 256 + c];
            a3 += sf[r * 512 + k + 3] * wf2[(k + 3) * 256 + c];
        }
        sz[r][cl] = bf2[c] + ((a0 + a1) + (a2 + a3));
    }
    __syncthreads();
    if (t < 32) {
        float s = 0.f, q = 0.f;
        for (int r = 0; r < 16; r++) { float v = sz[r][t]; s += v; q += v * v; }
        float mu = s * (1.f / Bb), var = q * (1.f / Bb) - mu * mu;
        float inv = rsqrtf(var + 1e-5f);
        float sc = gf2[blockIdx.x * 32 + t] * inv;
        scl[t] = sc; shf[t] = bef2[blockIdx.x * 32 + t] - sc * mu;
    }
    __syncthreads();
    #pragma unroll
    for (int q = 0; q < 2; q++) {
        int r = r0 + q * 8;
        g_fc2[r * 256 + c] = fmaxf(scl[cl] * sz[r][cl] + shf[cl], 0.f);
    }
}

__global__ void __launch_bounds__(256) k_mlp3(
    const float* __restrict__ wf3, const float* __restrict__ bf3,
    float* __restrict__ out) {
    __shared__ float sf[16 * 256];
    __shared__ float sl[16][11];
    int t = threadIdx.x;
    for (int i = t; i < 4096; i += 256) sf[i] = g_fc2[i];
    __syncthreads();
    if (t < Bb * NC) {
        int r = t / NC, j = t % NC;
        float a0 = 0.f, a1 = 0.f, a2 = 0.f, a3 = 0.f;
        for (int k = 0; k < 256; k += 4) {
            a0 += sf[r * 256 + k]     * wf3[(k)     * NC + j];
            a1 += sf[r * 256 + k + 1] * wf3[(k + 1) * NC + j];
            a2 += sf[r * 256 + k + 2] * wf3[(k + 2) * NC + j];
            a3 += sf[r * 256 + k + 3] * wf3[(k + 3) * NC + j];
        }
        sl[r][j] = bf3[j] + ((a0 + a1) + (a2 + a3));
    }
    __syncthreads();
    if (t < Bb) {
        float m = -1e30f;
        for (int j = 0; j < NC; j++) m = fmaxf(m, sl[t][j]);
        float s = 0.f;
        for (int j = 0; j < NC; j++) s += expf(sl[t][j] - m);
        float l = m + logf(s);
        for (int j = 0; j < NC; j++) out[t * NC + j] = sl[t][j] - l;
    }
}

// ---------------- launcher ----------------
extern "C" void kernel_launch(void* const* d_in, const int* in_sizes, int n_in,
                              void* d_out, int out_size) {
    const float* x      = (const float*)d_in[0];
    const float* ea     = (const float*)d_in[1];
    const float* w_edge = (const float*)d_in[2];
    const float* b_edge = (const float*)d_in[3];
    const float* w1  = (const float*)d_in[4];  const float* b1  = (const float*)d_in[5];
    const float* g1  = (const float*)d_in[6];  const float* be1 = (const float*)d_in[7];
    const float* w2  = (const float*)d_in[8];  const float* b2  = (const float*)d_in[9];
    const float* g2  = (const float*)d_in[10]; const float* be2 = (const float*)d_in[11];
    const float* w3  = (const float*)d_in[12]; const float* b3  = (const float*)d_in[13];
    const float* g3  = (const float*)d_in[14]; const float* be3 = (const float*)d_in[15];
    const float* wf1 = (const float*)d_in[16]; const float* bf1 = (const float*)d_in[17];
    const float* gf1 = (const float*)d_in[18]; const float* bef1= (const float*)d_in[19];
    const float* wf2 = (const float*)d_in[20]; const float* bf2 = (const float*)d_in[21];
    const float* gf2 = (const float*)d_in[22]; const float* bef2= (const float*)d_in[23];
    const float* wf3 = (const float*)d_in[24]; const float* bf3 = (const float*)d_in[25];
    const int*   ei    = (const int*)d_in[26];
    const int*   batch = (const int*)d_in[27];
    float* out = (float*)d_out;

    float *x16, *z1, *z2, *z3, *sum, *sq;
    cudaGetSymbolAddress((void**)&x16, g_x16);
    cudaGetSymbolAddress((void**)&z1,  g_z1);
    cudaGetSymbolAddress((void**)&z2,  g_z2);
    cudaGetSymbolAddress((void**)&z3,  g_z3);
    cudaGetSymbolAddress((void**)&sum, g_sum);
    cudaGetSymbolAddress((void**)&sq,  g_sq);

    const int T = 256;
    k_init<<<(Nn * 16 + T - 1) / T, T>>>(x);
    k_edge<<<(Ee / 2 + T - 1) / T, T>>>(ea, w_edge, b_edge, ei);
    k_scan<<<1, 1024>>>();
    k_scatter<<<(Ee / 2 + T - 1) / T, T>>>(ei);

    constexpr int LG = 768;  // 768 blocks * 8 warps * 2 rows = 12288
    k_layer<16, FIN, Hh, false, LG><<<LG, T>>>(x16, w1, b1, nullptr, nullptr,
                                               nullptr, nullptr, z1, sum, sq);
    k_layer<Hh, Hh, H2, true, LG><<<LG, T>>>(z1, w2, b2, g1, be1, sum, sq,
                                             z2, sum + 64, sq + 64);
    k_layer<H2, H2, H2, true, LG><<<LG, T>>>(z2, w3, b3, g2, be2, sum + 64, sq + 64,
                                             z3, sum + 128, sq + 128);

    k_pool<<<96, T>>>(z3, batch, g3, be3);

    k_mlp1<<<8, T>>>(wf1, bf1, gf1, bef1, out);
    k_mlp2<<<8, T>>>(wf2, bf2, gf2, bef2);
    k_mlp3<<<1, T>>>(wf3, bf3, out);
}

// round 8
// speedup vs baseline: 1.0632x; 1.0632x over previous
#include <cuda_runtime.h>
#include <math.h>

#define Nn   12288
#define Ee   393216
#define Bb   16
#define FIN  15
#define Hh   32
#define H2   64
#define NC   11

// ---------------- scratch (static device globals; no allocs) ----------------
__device__ float  g_ew[Ee];
__device__ int    g_cnt[Nn];
__device__ int    g_rowptr[Nn + 1];
__device__ int    g_woff[Nn];
__device__ float  g_deg[Nn];
__device__ float2 g_pack[Ee];          // (col bits, val = ew * dis[col])

__device__ float g_x16[Nn * 16];       // x padded 15 -> 16 for float4 gathers
__device__ float g_z1[Nn * Hh];
__device__ float g_z2[Nn * H2];
__device__ float g_z3[Nn * H2];

__device__ float g_sum[3 * 64];
__device__ float g_sq [3 * 64];

__device__ float g_emb[Bb * 64];
__device__ float g_fc1[Bb * 512];
__device__ float g_fc2[Bb * 256];

// ---------------- init + pad x ----------------
__global__ void k_init(const float* __restrict__ x) {
    int i = blockIdx.x * blockDim.x + threadIdx.x;
    if (i < Nn * 16) {
        int f = i & 15;
        g_x16[i] = (f < FIN) ? x[(i >> 4) * FIN + f] : 0.f;
    }
    if (i < Nn) { g_cnt[i] = 0; g_woff[i] = 0; g_deg[i] = 0.f; }
    if (i < 3 * 64) { g_sum[i] = 0.f; g_sq[i] = 0.f; }
    if (i < Bb * 64) g_emb[i] = 0.f;
}

__global__ void k_edge(const float* __restrict__ ea, const float* __restrict__ we,
                       const float* __restrict__ be, const int* __restrict__ ei) {
    int e = blockIdx.x * blockDim.x + threadIdx.x;
    if (e >= Ee) return;
    float2 a = ((const float2*)ea)[e];
    float t = a.x * we[0] + a.y * we[1] + be[0];
    float w = 1.f / (1.f + __expf(-t));
    g_ew[e] = w;
    int r = ei[e];
    atomicAdd(&g_cnt[r], 1);
    atomicAdd(&g_deg[r], w);
}

// single-block exclusive scan of g_cnt -> g_rowptr
__global__ void k_scan() {
    __shared__ int sh[1024];
    int t = threadIdx.x;
    const int C = Nn / 1024;  // 12
    int base = t * C;
    int pre[C];
    int s = 0;
    #pragma unroll
    for (int c = 0; c < C; c++) { pre[c] = s; s += g_cnt[base + c]; }
    sh[t] = s;
    __syncthreads();
    for (int d = 1; d < 1024; d <<= 1) {
        int v = (t >= d) ? sh[t - d] : 0;
        __syncthreads();
        sh[t] += v;
        __syncthreads();
    }
    int off = (t > 0) ? sh[t - 1] : 0;
    #pragma unroll
    for (int c = 0; c < C; c++) g_rowptr[base + c] = off + pre[c];
    if (t == 1023) g_rowptr[Nn] = sh[1023];
}

__global__ void k_scatter(const int* __restrict__ ei) {
    int e = blockIdx.x * blockDim.x + threadIdx.x;
    if (e >= Ee) return;
    int r = ei[e];
    int c = ei[Ee + e];
    float val = g_ew[e] * rsqrtf(1.f + g_deg[c]);
    int p = g_rowptr[r] + atomicAdd(&g_woff[r], 1);
    g_pack[p] = make_float2(__int_as_float(c), val);
}

// ---- fused GCN layer: (BN+ReLU of prev inline) -> SpMM -> GEMM -> BN stats ----
// Warp splits into EPW = 32/LPE edge slots, LPE = FI/4 lanes each; each slot
// gathers a full feature row as float4s. Full 32-edge chunks use a fully
// unrolled body (no predication, high MLP); the <32 remainder runs one padded
// pass (pad entries: col=0, w=0 -> zero contribution, row-0 gathers L1-hit).
template <int FI, int FIeff, int FO, bool BN_IN, int GRID>
__global__ void __launch_bounds__(256) k_layer(
    const float* __restrict__ in,
    const float* __restrict__ W,         // [FIeff,FO]
    const float* __restrict__ bias,
    const float* __restrict__ gam, const float* __restrict__ bet,
    const float* __restrict__ sum_in, const float* __restrict__ sq_in,
    float* __restrict__ out,
    float* __restrict__ sum_out, float* __restrict__ sq_out)
{
    constexpr int LPE = FI / 4;
    constexpr int EPW = 32 / LPE;
    __shared__ float  sW[FIeff * FO];
    __shared__ float4 sRow4[8][16];
    __shared__ float  sScale[FI], sShift[FI];
    __shared__ float  sSum[FO], sSq[FO];
    int tid = threadIdx.x;
    for (int i = tid; i < FIeff * FO; i += 256) sW[i] = W[i];
    if (tid < FO) { sSum[tid] = 0.f; sSq[tid] = 0.f; }
    if (tid < FI) {
        if (BN_IN) {
            float mu  = sum_in[tid] * (1.f / (float)Nn);
            float var = sq_in[tid]  * (1.f / (float)Nn) - mu * mu;
            float inv = rsqrtf(var + 1e-5f);
            float sc  = gam[tid] * inv;
            sScale[tid] = sc;
            sShift[tid] = bet[tid] - sc * mu;
        } else { sScale[tid] = 1.f; sShift[tid] = 0.f; }
    }
    __syncthreads();

    int warp = tid >> 5, lane = tid & 31;
    int eh = lane / LPE;        // edge slot
    int fl = lane % LPE;        // feature quad
    float4 sc4, sh4;
    sc4.x = sScale[4*fl+0]; sc4.y = sScale[4*fl+1];
    sc4.z = sScale[4*fl+2]; sc4.w = sScale[4*fl+3];
    sh4.x = sShift[4*fl+0]; sh4.y = sShift[4*fl+1];
    sh4.z = sShift[4*fl+2]; sh4.w = sShift[4*fl+3];
    float b0 = (lane < FO) ? bias[lane] : 0.f;
    float b1 = (FO > 32) ? bias[lane + 32] : 0.f;

    const float4* in4 = (const float4*)in;
    const int RPW = Nn / (GRID * 8);
    int rowBase = (blockIdx.x * 8 + warp) * RPW;

    for (int rr = 0; rr < RPW; rr++) {
        int row = rowBase + rr;
        float d = rsqrtf(1.f + g_deg[row]);
        int s = g_rowptr[row], e = g_rowptr[row + 1];

        float4 acc = make_float4(0.f, 0.f, 0.f, 0.f);
        if (eh == 0) {   // self-loop (weight 1): d * bnrelu(in[row])
            float4 v = in4[row * LPE + fl];
            if (BN_IN) {
                v.x = fmaxf(fmaf(sc4.x, v.x, sh4.x), 0.f);
                v.y = fmaxf(fmaf(sc4.y, v.y, sh4.y), 0.f);
                v.z = fmaxf(fmaf(sc4.z, v.z, sh4.z), 0.f);
                v.w = fmaxf(fmaf(sc4.w, v.w, sh4.w), 0.f);
            }
            acc.x = d * v.x; acc.y = d * v.y; acc.z = d * v.z; acc.w = d * v.w;
        }

        int kend = s + ((e - s) & ~31);
        // full chunks: fully unrolled, unconditional loads
        for (int k = s; k < kend; k += 32) {
            float2 pk = __ldg(&g_pack[k + lane]);
            #pragma unroll
            for (int j = 0; j < 32; j += EPW) {
                int src = j + eh;
                int   c = __float_as_int(__shfl_sync(0xffffffffu, pk.x, src));
                float w = __shfl_sync(0xffffffffu, pk.y, src);
                float4 v = in4[c * LPE + fl];
                if (BN_IN) {
                    v.x = fmaxf(fmaf(sc4.x, v.x, sh4.x), 0.f);
                    v.y = fmaxf(fmaf(sc4.y, v.y, sh4.y), 0.f);
                    v.z = fmaxf(fmaf(sc4.z, v.z, sh4.z), 0.f);
                    v.w = fmaxf(fmaf(sc4.w, v.w, sh4.w), 0.f);
                }
                acc.x = fmaf(w, v.x, acc.x);
                acc.y = fmaf(w, v.y, acc.y);
                acc.z = fmaf(w, v.z, acc.z);
                acc.w = fmaf(w, v.w, acc.w);
            }
        }
        // remainder (< 32 edges): padded groups, zero-weight entries no-op
        int rem = e - kend;
        if (rem > 0) {
            float2 pk = (lane < rem) ? __ldg(&g_pack[kend + lane])
                                     : make_float2(__int_as_float(0), 0.f);
            for (int j = 0; j < rem; j += EPW) {
                int src = j + eh;
                int   c = __float_as_int(__shfl_sync(0xffffffffu, pk.x, src));
                float w = __shfl_sync(0xffffffffu, pk.y, src);
                float4 v = in4[c * LPE + fl];
                if (BN_IN) {
                    v.x = fmaxf(fmaf(sc4.x, v.x, sh4.x), 0.f);
                    v.y = fmaxf(fmaf(sc4.y, v.y, sh4.y), 0.f);
                    v.z = fmaxf(fmaf(sc4.z, v.z, sh4.z), 0.f);
                    v.w = fmaxf(fmaf(sc4.w, v.w, sh4.w), 0.f);
                }
                acc.x = fmaf(w, v.x, acc.x);
                acc.y = fmaf(w, v.y, acc.y);
                acc.z = fmaf(w, v.z, acc.z);
                acc.w = fmaf(w, v.w, acc.w);
            }
        }
        // reduce over edge slots
        #pragma unroll
        for (int o = LPE; o < 32; o <<= 1) {
            acc.x += __shfl_xor_sync(0xffffffffu, acc.x, o);
            acc.y += __shfl_xor_sync(0xffffffffu, acc.y, o);
            acc.z += __shfl_xor_sync(0xffffffffu, acc.z, o);
            acc.w += __shfl_xor_sync(0xffffffffu, acc.w, o);
        }
        acc.x *= d; acc.y *= d; acc.z *= d; acc.w *= d;
        if (eh == 0) sRow4[warp][fl] = acc;
        __syncwarp();
        const float* h = (const float*)&sRow4[warp][0];
        float o0 = b0, o1 = b1;
        #pragma unroll
        for (int f = 0; f < FIeff; f++) {
            float hv = h[f];
            o0 = fmaf(hv, sW[f * FO + lane], o0);
            if (FO > 32) o1 = fmaf(hv, sW[f * FO + lane + 32], o1);
        }
        __syncwarp();
        if (lane < FO) {
            out[row * FO + lane] = o0;
            atomicAdd(&sSum[lane], o0);
            atomicAdd(&sSq[lane],  o0 * o0);
        }
        if (FO > 32) {
            out[row * FO + lane + 32] = o1;
            atomicAdd(&sSum[lane + 32], o1);
            atomicAdd(&sSq[lane + 32],  o1 * o1);
        }
    }
    __syncthreads();
    if (tid < FO) {
        atomicAdd(&sum_out[tid], sSum[tid]);
        atomicAdd(&sq_out[tid],  sSq[tid]);
    }
}

// ---------------- max pool: sorted-batch segment flush ----------------
__global__ void __launch_bounds__(256) k_pool(
    const float* __restrict__ z3, const int* __restrict__ batch,
    const float* __restrict__ gam, const float* __restrict__ bet) {
    __shared__ float scl[64], shf[64];
    int t = threadIdx.x;
    if (t < 64) {
        float mu  = g_sum[128 + t] * (1.f / (float)Nn);
        float var = g_sq [128 + t] * (1.f / (float)Nn) - mu * mu;
        float inv = rsqrtf(var + 1e-5f);
        float sc  = gam[t] * inv;
        scl[t] = sc; shf[t] = bet[t] - sc * mu;
    }
    __syncthreads();
    int f  = t & 63;
    int r0 = blockIdx.x * 128 + (t >> 6);
    float sc = scl[f], sh = shf[f];
    int curb = -1; float cm = 0.f;
    for (int r = r0; r < blockIdx.x * 128 + 128; r += 4) {
        int b = batch[r];
        float v = fmaxf(fmaf(sc, z3[r * 64 + f], sh), 0.f);
        if (b != curb) {
            if (curb >= 0) atomicMax((int*)&g_emb[curb * 64 + f], __float_as_int(cm));
            curb = b; cm = v;
        } else cm = fmaxf(cm, v);
    }
    if (curb >= 0) atomicMax((int*)&g_emb[curb * 64 + f], __float_as_int(cm));
}

// ---------------- MLP head ----------------
__global__ void __launch_bounds__(256) k_mlp1(
    const float* __restrict__ wf1, const float* __restrict__ bf1,
    const float* __restrict__ gf1, const float* __restrict__ bef1,
    float* __restrict__ out) {
    __shared__ float se[16 * 64];
    __shared__ float sz[16][64];
    __shared__ float scl[64], shf[64];
    int t = threadIdx.x;
    for (int i = t; i < 1024; i += 256) se[i] = g_emb[i];
    __syncthreads();
    int cl = t & 63;
    int r0 = t >> 6;
    int c = blockIdx.x * 64 + cl;
    #pragma unroll
    for (int q = 0; q < 4; q++) {
        int r = r0 + q * 4;
        float a0 = 0.f, a1 = 0.f, a2 = 0.f, a3 = 0.f;
        #pragma unroll
        for (int k = 0; k < 64; k += 4) {
            a0 += se[r * 64 + k]     * wf1[(k)     * 512 + c];
            a1 += se[r * 64 + k + 1] * wf1[(k + 1) * 512 + c];
            a2 += se[r * 64 + k + 2] * wf1[(k + 2) * 512 + c];
            a3 += se[r * 64 + k + 3] * wf1[(k + 3) * 512 + c];
        }
        sz[r][cl] = bf1[c] + ((a0 + a1) + (a2 + a3));
    }
    __syncthreads();
    if (t < 64) {
        float s = 0.f, q = 0.f;
        for (int r = 0; r < 16; r++) { float v = sz[r][t]; s += v; q += v * v; }
        float mu = s * (1.f / Bb), var = q * (1.f / Bb) - mu * mu;
        float inv = rsqrtf(var + 1e-5f);
        float sc = gf1[blockIdx.x * 64 + t] * inv;
        scl[t] = sc; shf[t] = bef1[blockIdx.x * 64 + t] - sc * mu;
    }
    __syncthreads();
    #pragma unroll
    for (int q = 0; q < 4; q++) {
        int r = r0 + q * 4;
        g_fc1[r * 512 + c] = fmaxf(scl[cl] * sz[r][cl] + shf[cl], 0.f);
    }
    if (blockIdx.x == 0)
        for (int i = t; i < 1024; i += 256) out[Bb * NC + i] = se[i];
}

__global__ void __launch_bounds__(256) k_mlp2(
    const float* __restrict__ wf2, const float* __restrict__ bf2,
    const float* __restrict__ gf2, const float* __restrict__ bef2) {
    __shared__ float sf[16 * 512];
    __shared__ float sz[16][32];
    __shared__ float scl[32], shf[32];
    int t = threadIdx.x;
    for (int i = t; i < 8192; i += 256) sf[i] = g_fc1[i];
    __syncthreads();
    int cl = t & 31;
    int r0 = t >> 5;
    int c = blockIdx.x * 32 + cl;
    #pragma unroll
    for (int q = 0; q < 2; q++) {
        int r = r0 + q * 8;
        float a0 = 0.f, a1 = 0.f, a2 = 0.f, a3 = 0.f;
        for (int k = 0; k < 512; k += 4) {
            a0 += sf[r * 512 + k]     * wf2[(k)     * 256 + c];
            a1 += sf[r * 512 + k + 1] * wf2[(k + 1) * 256 + c];
            a2 += sf[r * 512 + k + 2] * wf2[(k + 2) * 256 + c];
            a3 += sf[r * 512 + k + 3] * wf2[(k + 3) * 256 + c];
        }
        sz[r][cl] = bf2[c] + ((a0 + a1) + (a2 + a3));
    }
    __syncthreads();
    if (t < 32) {
        float s = 0.f, q = 0.f;
        for (int r = 0; r < 16; r++) { float v = sz[r][t]; s += v; q += v * v; }
        float mu = s * (1.f / Bb), var = q * (1.f / Bb) - mu * mu;
        float inv = rsqrtf(var + 1e-5f);
        float sc = gf2[blockIdx.x * 32 + t] * inv;
        scl[t] = sc; shf[t] = bef2[blockIdx.x * 32 + t] - sc * mu;
    }
    __syncthreads();
    #pragma unroll
    for (int q = 0; q < 2; q++) {
        int r = r0 + q * 8;
        g_fc2[r * 256 + c] = fmaxf(scl[cl] * sz[r][cl] + shf[cl], 0.f);
    }
}

__global__ void __launch_bounds__(256) k_mlp3(
    const float* __restrict__ wf3, const float* __restrict__ bf3,
    float* __restrict__ out) {
    __shared__ float sf[16 * 256];
    __shared__ float sl[16][11];
    int t = threadIdx.x;
    for (int i = t; i < 4096; i += 256) sf[i] = g_fc2[i];
    __syncthreads();
    if (t < Bb * NC) {
        int r = t / NC, j = t % NC;
        float a0 = 0.f, a1 = 0.f, a2 = 0.f, a3 = 0.f;
        for (int k = 0; k < 256; k += 4) {
            a0 += sf[r * 256 + k]     * wf3[(k)     * NC + j];
            a1 += sf[r * 256 + k + 1] * wf3[(k + 1) * NC + j];
            a2 += sf[r * 256 + k + 2] * wf3[(k + 2) * NC + j];
            a3 += sf[r * 256 + k + 3] * wf3[(k + 3) * NC + j];
        }
        sl[r][j] = bf3[j] + ((a0 + a1) + (a2 + a3));
    }
    __syncthreads();
    if (t < Bb) {
        float m = -1e30f;
        for (int j = 0; j < NC; j++) m = fmaxf(m, sl[t][j]);
        float s = 0.f;
        for (int j = 0; j < NC; j++) s += expf(sl[t][j] - m);
        float l = m + logf(s);
        for (int j = 0; j < NC; j++) out[t * NC + j] = sl[t][j] - l;
    }
}

// ---------------- launcher ----------------
extern "C" void kernel_launch(void* const* d_in, const int* in_sizes, int n_in,
                              void* d_out, int out_size) {
    const float* x      = (const float*)d_in[0];
    const float* ea     = (const float*)d_in[1];
    const float* w_edge = (const float*)d_in[2];
    const float* b_edge = (const float*)d_in[3];
    const float* w1  = (const float*)d_in[4];  const float* b1  = (const float*)d_in[5];
    const float* g1  = (const float*)d_in[6];  const float* be1 = (const float*)d_in[7];
    const float* w2  = (const float*)d_in[8];  const float* b2  = (const float*)d_in[9];
    const float* g2  = (const float*)d_in[10]; const float* be2 = (const float*)d_in[11];
    const float* w3  = (const float*)d_in[12]; const float* b3  = (const float*)d_in[13];
    const float* g3  = (const float*)d_in[14]; const float* be3 = (const float*)d_in[15];
    const float* wf1 = (const float*)d_in[16]; const float* bf1 = (const float*)d_in[17];
    const float* gf1 = (const float*)d_in[18]; const float* bef1= (const float*)d_in[19];
    const float* wf2 = (const float*)d_in[20]; const float* bf2 = (const float*)d_in[21];
    const float* gf2 = (const float*)d_in[22]; const float* bef2= (const float*)d_in[23];
    const float* wf3 = (const float*)d_in[24]; const float* bf3 = (const float*)d_in[25];
    const int*   ei    = (const int*)d_in[26];
    const int*   batch = (const int*)d_in[27];
    float* out = (float*)d_out;

    float *x16, *z1, *z2, *z3, *sum, *sq;
    cudaGetSymbolAddress((void**)&x16, g_x16);
    cudaGetSymbolAddress((void**)&z1,  g_z1);
    cudaGetSymbolAddress((void**)&z2,  g_z2);
    cudaGetSymbolAddress((void**)&z3,  g_z3);
    cudaGetSymbolAddress((void**)&sum, g_sum);
    cudaGetSymbolAddress((void**)&sq,  g_sq);

    const int T = 256;
    k_init<<<(Nn * 16 + T - 1) / T, T>>>(x);
    k_edge<<<(Ee + T - 1) / T, T>>>(ea, w_edge, b_edge, ei);
    k_scan<<<1, 1024>>>();
    k_scatter<<<(Ee + T - 1) / T, T>>>(ei);

    constexpr int LG = 768;  // 768 blocks * 8 warps * 2 rows = 12288
    k_layer<16, FIN, Hh, false, LG><<<LG, T>>>(x16, w1, b1, nullptr, nullptr,
                                               nullptr, nullptr, z1, sum, sq);
    k_layer<Hh, Hh, H2, true, LG><<<LG, T>>>(z1, w2, b2, g1, be1, sum, sq,
                                             z2, sum + 64, sq + 64);
    k_layer<H2, H2, H2, true, LG><<<LG, T>>>(z2, w3, b3, g2, be2, sum + 64, sq + 64,
                                             z3, sum + 128, sq + 128);

    k_pool<<<96, T>>>(z3, batch, g3, be3);

    k_mlp1<<<8, T>>>(wf1, bf1, gf1, bef1, out);
    k_mlp2<<<8, T>>>(wf2, bf2, gf2, bef2);
    k_mlp3<<<1, T>>>(wf3, bf3, out);
}